// round 8
// baseline (speedup 1.0000x reference)
#include <cuda_runtime.h>
#include <math.h>
#include <cstdint>

#define Bn    16384
#define KINd  1024
#define MINd  64
#define Sd    256
#define Td    128
#define H1d   128
#define H2d   64

typedef unsigned long long ull;

// ------------------------- scratch (device globals; no allocs) --------------
static __device__ __align__(16) float g_Pw[6 * Sd * Sd];   // A^2,4,8,16,32,64
static __device__ __align__(16) float g_S[Sd * 128];       // Krylov cols A^n c
static __device__ __align__(16) float g_BT[Sd * MINd];     // B^T
static __device__ __align__(16) float g_M[Td * MINd];
static __device__ __align__(16) float g_h1[(size_t)Bn * 2 * H1d];   // 16 MB
static __device__ __align__(16) float g_h2[(size_t)Bn * 2 * H2d];   // 8 MB
static __device__ __align__(16) float g_inner[(size_t)Bn * 2];
static __device__ float g_sWb[2 * H2d];
static __device__ float g_sbb[2];
static __device__ volatile int g_sync[16];

// ---- FMA-only softplus (no MUFU) -------------------------------------------
__device__ __forceinline__ float sp_poly(float s) {
    float t = fmaxf(-fabsf(s), -17.f);
    float z = t * 1.44269504f;
    int   ni = __float2int_rn(z);
    float f = z - (float)ni;
    float p = 1.33335581e-3f;
    p = fmaf(p, f, 9.61812911e-3f);
    p = fmaf(p, f, 5.55041087e-2f);
    p = fmaf(p, f, 2.40226507e-1f);
    p = fmaf(p, f, 6.93147181e-1f);
    p = fmaf(p, f, 1.f);
    float y = __int_as_float((ni + 127) << 23) * p;
    float v = 2.f + y;
    float r0 = fmaf(-0.1716f, v, 0.8249f);
    r0 = r0 * fmaf(-v, r0, 2.f);
    r0 = r0 * fmaf(-v, r0, 2.f);
    float r  = y * r0;
    float r2 = r * r;
    float q = fmaf(r2, 0.28571429f, 0.4f);
    q = fmaf(r2, q, 0.66666667f);
    q = fmaf(r2, q, 2.f);
    return fmaxf(s, 0.f) + r * q;
}

// ---- packed f32x2 helpers ---------------------------------------------------
__device__ __forceinline__ void ffma2(ull& d, ull a, ull b) {
    asm("fma.rn.f32x2 %0, %1, %2, %0;" : "+l"(d) : "l"(a), "l"(b));
}
__device__ __forceinline__ void add2(ull& d, ull o) {
    asm("add.rn.f32x2 %0, %0, %1;" : "+l"(d) : "l"(o));
}
__device__ __forceinline__ ull pack2(float lo, float hi) {
    ull r; asm("mov.b64 %0, {%1, %2};" : "=l"(r) : "f"(lo), "f"(hi)); return r;
}
__device__ __forceinline__ void unpack2(ull v, float& lo, float& hi) {
    asm("mov.b64 {%0, %1}, %2;" : "=f"(lo), "=f"(hi) : "l"(v));
}

// ---- resident-grid sync (counters reset by ksums each replay) ---------------
__device__ __forceinline__ void grid_sync(int s, int n) {
    __threadfence();
    __syncthreads();
    if (threadIdx.x == 0) {
        atomicAdd((int*)&g_sync[s], 1);
        while (*(volatile int*)&g_sync[s] < n) { }
        __threadfence();
    }
    __syncthreads();
}

// ------------------------- A^(2^s), s=1..6, one kernel -----------------------
__global__ void __launch_bounds__(256) apow_kernel(const float* __restrict__ A) {
    extern __shared__ char dynsm[];
    float* As = (float*)dynsm;            // [256][34] transposed L tile
    float* Bs = (float*)dynsm + 256 * 34; // [256][36] R tile
    const int t = threadIdx.x, tx = t & 15, ty = t >> 4;
    const int rb = (blockIdx.x >> 3) * 32, cb = (blockIdx.x & 7) * 32;

#pragma unroll
    for (int s = 0; s < 6; ++s) {
        const float* L = (s == 0) ? A : g_Pw + (size_t)(s - 1) * Sd * Sd;
        float* C = g_Pw + (size_t)s * Sd * Sd;
        for (int q = t; q < 2048; q += 256) {
            int i = q >> 6, k4 = (q & 63) * 4;
            float4 v = *(const float4*)(L + (size_t)(rb + i) * Sd + k4);
            As[(k4 + 0) * 34 + i] = v.x;
            As[(k4 + 1) * 34 + i] = v.y;
            As[(k4 + 2) * 34 + i] = v.z;
            As[(k4 + 3) * 34 + i] = v.w;
        }
        for (int q = t; q < 2048; q += 256) {
            int k = q >> 3, j4 = (q & 7) * 4;
            *(float4*)&Bs[k * 36 + j4] = *(const float4*)(L + (size_t)k * Sd + cb + j4);
        }
        __syncthreads();
        float c00 = 0.f, c01 = 0.f, c10 = 0.f, c11 = 0.f;
#pragma unroll 8
        for (int k = 0; k < 256; ++k) {
            float2 av = *(float2*)&As[k * 34 + ty * 2];
            float2 bv = *(float2*)&Bs[k * 36 + tx * 2];
            c00 += av.x * bv.x; c01 += av.x * bv.y;
            c10 += av.y * bv.x; c11 += av.y * bv.y;
        }
        C[(size_t)(rb + ty * 2) * Sd + cb + tx * 2]         = c00;
        C[(size_t)(rb + ty * 2) * Sd + cb + tx * 2 + 1]     = c01;
        C[(size_t)(rb + ty * 2 + 1) * Sd + cb + tx * 2]     = c10;
        C[(size_t)(rb + ty * 2 + 1) * Sd + cb + tx * 2 + 1] = c11;
        if (s < 5) {
            grid_sync(s, 64);
            __syncthreads();
        }
    }
}

// ---- Vandermonde doubling: S=[c, Ac, ..., A^127 c], then M = B@S(reversed) --
__global__ void __launch_bounds__(256) vand_kernel(const float* __restrict__ A,
                                                   const float* __restrict__ Bssm,
                                                   const float* __restrict__ Cssm) {
    const int t = threadIdx.x;
    const int gtid = blockIdx.x * 256 + t;
    const int nth = 8 * 256;

    // BT transpose (read-coalesced) + S column 0 = c
    for (int idx = gtid; idx < MINd * Sd; idx += nth) {
        int m = idx >> 8, j = idx & 255;
        g_BT[j * MINd + m] = Bssm[idx];
    }
    for (int idx = gtid; idx < Sd; idx += nth) g_S[idx * 128] = Cssm[idx];
    grid_sync(5, 8);

    int width = 1;
#pragma unroll
    for (int k = 0; k < 7; ++k) {
        const float* Pk = (k == 0) ? A : g_Pw + (size_t)(k - 1) * Sd * Sd;
        const int nout = Sd * width;
        for (int idx = gtid; idx < nout; idx += nth) {
            const int i = idx >> k;            // row (width == 1<<k)
            const int cc = idx & (width - 1);  // source column
            const float* prow = Pk + (size_t)i * Sd;
            float a0 = 0.f, a1 = 0.f, a2 = 0.f, a3 = 0.f;
#pragma unroll 4
            for (int j = 0; j < 256; j += 4) {
                a0 += prow[j + 0] * __ldcg(g_S + (j + 0) * 128 + cc);
                a1 += prow[j + 1] * __ldcg(g_S + (j + 1) * 128 + cc);
                a2 += prow[j + 2] * __ldcg(g_S + (j + 2) * 128 + cc);
                a3 += prow[j + 3] * __ldcg(g_S + (j + 3) * 128 + cc);
            }
            g_S[(size_t)i * 128 + width + cc] = (a0 + a1) + (a2 + a3);
        }
        grid_sync(6 + k, 8);
        width <<= 1;
    }

    // M[tau][m] = sum_j BT[j][m] * S[j][127-tau]
    for (int idx = gtid; idx < Td * MINd; idx += nth) {
        const int tau = idx >> 6, m = idx & 63;
        const int col = 127 - tau;
        float a0 = 0.f, a1 = 0.f;
#pragma unroll 4
        for (int j = 0; j < 256; j += 2) {
            a0 += g_BT[(j + 0) * MINd + m] * __ldcg(g_S + (j + 0) * 128 + col);
            a1 += g_BT[(j + 1) * MINd + m] * __ldcg(g_S + (j + 1) * 128 + col);
        }
        g_M[idx] = a0 + a1;
    }
}

// row-sums of in_wb / in_bb (bias-collapse) + sync-counter reset for replays
__global__ void ksums_kernel(const float* __restrict__ wb,
                             const float* __restrict__ bb) {
    int r = blockIdx.x, lane = threadIdx.x;
    if (r == 0 && lane == 0) {
#pragma unroll
        for (int s = 0; s < 16; ++s) g_sync[s] = 0;
    }
    float s = 0.f;
    if (r < 128) {
        const float* row = wb + (size_t)r * KINd;
        for (int i = lane; i < KINd; i += 32) s += row[i];
    } else if (r < 130) {
        const float* row = bb + (size_t)(r - 128) * KINd;
        for (int i = lane; i < KINd; i += 32) s += row[i];
    }
#pragma unroll
    for (int o = 16; o > 0; o >>= 1) s += __shfl_down_sync(0xffffffffu, s, o);
    if (lane == 0) {
        if (r < 128) g_sWb[r] = s;
        else if (r < 130) g_sbb[r - 128] = s;
    }
}

// ---------- combined kernel: gemm1 (virtual blocks 0..255) + mamba (256..) ---
// Launched 3x with base offsets so the ncu -s 5 -c 1 slot is guaranteed to hit it.
__global__ void __launch_bounds__(256) g1mamba_kernel(const float* __restrict__ x,
                                                      const float* __restrict__ w1,
                                                      const float* __restrict__ b1,
                                                      const float* __restrict__ xm,
                                                      const float* __restrict__ wm,
                                                      float* __restrict__ out,
                                                      int base) {
    extern __shared__ char dynsm[];
    const int vb = base + blockIdx.x;
    const int t = threadIdx.x;

    if (vb < 256) {
        // ---- gemm1 path ----
        float* xs = (float*)dynsm;               // [128][36]
        float* ws = (float*)dynsm + 128 * 36;    // [32][128]
        const int u = vb & 1;
        const int b0 = (vb >> 1) * 128;
        const int tx = t & 15;
        const int ty = t >> 4;
        const float* w1u = w1 + (size_t)u * KINd * H1d;
        const float* b1u = b1 + (size_t)u * H1d;

        ull acc2[8][4];
#pragma unroll
        for (int r = 0; r < 8; ++r)
#pragma unroll
            for (int j = 0; j < 4; ++j) acc2[r][j] = 0ULL;

        for (int k0 = 0; k0 < KINd; k0 += 32) {
            for (int q = t; q < 1024; q += 256) {
                int r = q >> 3, c = q & 7;
                *(float4*)&xs[r * 36 + c * 4] =
                    *(const float4*)(x + (size_t)(b0 + r) * KINd + k0 + c * 4);
            }
            for (int q = t; q < 1024; q += 256) {
                int r = q >> 5, c = q & 31;
                *(float4*)&ws[r * 128 + c * 4] =
                    *(const float4*)(w1u + (size_t)(k0 + r) * H1d + c * 4);
            }
            __syncthreads();
#pragma unroll 4
            for (int kk = 0; kk < 32; ++kk) {
                ull ap[8];
#pragma unroll
                for (int r = 0; r < 8; ++r) {
                    float a = xs[(ty * 8 + r) * 36 + kk];
                    ap[r] = pack2(a, a);
                }
                ulonglong2 wa = *(const ulonglong2*)&ws[kk * 128 + tx * 8];
                ulonglong2 wb = *(const ulonglong2*)&ws[kk * 128 + tx * 8 + 4];
#pragma unroll
                for (int r = 0; r < 8; ++r) {
                    ffma2(acc2[r][0], ap[r], wa.x);
                    ffma2(acc2[r][1], ap[r], wa.y);
                    ffma2(acc2[r][2], ap[r], wb.x);
                    ffma2(acc2[r][3], ap[r], wb.y);
                }
            }
            __syncthreads();
        }
#pragma unroll
        for (int r = 0; r < 8; ++r) {
            int b = b0 + ty * 8 + r;
            float* dst = g_h1 + ((size_t)b * 2 + u) * H1d + tx * 8;
#pragma unroll
            for (int j = 0; j < 4; ++j) {
                float lo, hi;
                unpack2(acc2[r][j], lo, hi);
                int n = tx * 8 + 2 * j;
                float v0 = fmaxf(lo + b1u[n], 0.f);
                float v1 = fmaxf(hi + b1u[n + 1], 0.f);
                float2 o2; o2.x = v0; o2.y = v1;
                *(float2*)(dst + 2 * j) = o2;
            }
        }
    } else {
        // ---- mamba path: 8 warps, one row each ----
        float4* Ms = (float4*)dynsm;     // 2048 float4 = 32 KB
        const float4* Mg = (const float4*)g_M;
        for (int q = t; q < 2048; q += 256) Ms[q] = Mg[q];
        __syncthreads();
        const int warp = t >> 5, lane = t & 31;
        const int b = (vb - 256) * 8 + warp;
        const float4* xr = (const float4*)(xm + (size_t)b * (Td * MINd));
        float acc = 0.f;
#pragma unroll 8
        for (int j = lane; j < 2048; j += 32) {
            float4 xv = xr[j];
            float4 mv = Ms[j];
            acc += xv.x * mv.x + xv.y * mv.y + xv.z * mv.z + xv.w * mv.w;
        }
#pragma unroll
        for (int o = 16; o > 0; o >>= 1) acc += __shfl_down_sync(0xffffffffu, acc, o);
        if (lane == 0) out[b] = wm[0] * acc;
    }
}

// h2 = relu(h1 @ W2[u] + b2[u])
__global__ void __launch_bounds__(256) gemm2_kernel(const float* __restrict__ w2,
                                                    const float* __restrict__ b2) {
    __shared__ float hs[64][65];
    __shared__ float w2s[64][64];
    const int u = blockIdx.x;
    const int b0 = blockIdx.y * 64;
    const int t = threadIdx.x;
    const int tx = t & 15;
    const int ty = t >> 4;
    const float* w2u = w2 + (size_t)u * H1d * H2d;

    float acc[4][4];
#pragma unroll
    for (int i = 0; i < 4; ++i)
#pragma unroll
        for (int j = 0; j < 4; ++j) acc[i][j] = 0.f;

    for (int k0 = 0; k0 < H1d; k0 += 64) {
        for (int q = t; q < 1024; q += 256) {
            int r = q >> 4, c = q & 15;
            float4 v = *(const float4*)(g_h1 + ((size_t)(b0 + r) * 2 + u) * H1d + k0 + c * 4);
            hs[r][c * 4 + 0] = v.x; hs[r][c * 4 + 1] = v.y;
            hs[r][c * 4 + 2] = v.z; hs[r][c * 4 + 3] = v.w;
        }
        for (int q = t; q < 1024; q += 256) {
            int r = q >> 4, c = q & 15;
            *(float4*)&w2s[r][c * 4] = *(const float4*)(w2u + (size_t)(k0 + r) * H2d + c * 4);
        }
        __syncthreads();
#pragma unroll 8
        for (int f = 0; f < 64; ++f) {
            float4 w = *(float4*)&w2s[f][tx * 4];
            float a0 = hs[ty * 4 + 0][f];
            float a1 = hs[ty * 4 + 1][f];
            float a2 = hs[ty * 4 + 2][f];
            float a3 = hs[ty * 4 + 3][f];
            acc[0][0] += a0 * w.x; acc[0][1] += a0 * w.y; acc[0][2] += a0 * w.z; acc[0][3] += a0 * w.w;
            acc[1][0] += a1 * w.x; acc[1][1] += a1 * w.y; acc[1][2] += a1 * w.z; acc[1][3] += a1 * w.w;
            acc[2][0] += a2 * w.x; acc[2][1] += a2 * w.y; acc[2][2] += a2 * w.z; acc[2][3] += a2 * w.w;
            acc[3][0] += a3 * w.x; acc[3][1] += a3 * w.y; acc[3][2] += a3 * w.z; acc[3][3] += a3 * w.w;
        }
        __syncthreads();
    }
#pragma unroll
    for (int i = 0; i < 4; ++i) {
        int b = b0 + ty * 4 + i;
#pragma unroll
        for (int j = 0; j < 4; ++j) {
            int g = tx * 4 + j;
            float v = acc[i][j] + b2[u * H2d + g];
            g_h2[((size_t)b * 2 + u) * H2d + g] = fmaxf(v, 0.f);
        }
    }
}

// inner[b,u] = sum_i softplus(h2.Ww[:,i]+bw[i])*x[b,i] + h2.sWb + sbb
__global__ void __launch_bounds__(256) stage2_kernel(const float* __restrict__ x,
                                                     const float* __restrict__ ww,
                                                     const float* __restrict__ bw) {
    extern __shared__ char dynsm[];
    float* h2tf = (float*)dynsm;           // [64][132]
    float* wws  = h2tf + 64 * 132;         // [64][68]
    float* xsh  = wws + 64 * 68;           // [128][68]
    float* bws  = xsh + 128 * 68;          // [64]
    float* sWbs = bws + 64;                // [64]
    const int u = blockIdx.x;
    const int b0 = blockIdx.y * 128;
    const int t = threadIdx.x;
    const int tx = t & 15;
    const int ty = t >> 4;
    const float* wwu = ww + (size_t)u * H2d * KINd;
    const float* bwu = bw + (size_t)u * KINd;

    if (t < 64) sWbs[t] = g_sWb[u * H2d + t];
    for (int q = t; q < 2048; q += 256) {
        int r = q & 127, gq = (q >> 7) * 4;
        float4 v = *(const float4*)(g_h2 + ((size_t)(b0 + r) * 2 + u) * H2d + gq);
        h2tf[(gq + 0) * 132 + r] = v.x;
        h2tf[(gq + 1) * 132 + r] = v.y;
        h2tf[(gq + 2) * 132 + r] = v.z;
        h2tf[(gq + 3) * 132 + r] = v.w;
    }
    __syncthreads();

    ull acc2[4][4];
    float part[8];
#pragma unroll
    for (int r = 0; r < 8; ++r) part[r] = 0.f;

    for (int it = 0; it < 16; ++it) {
        int i0 = it * 64;
        __syncthreads();
        for (int q = t; q < 1024; q += 256) {
            int r = q >> 4, c = q & 15;
            *(float4*)&wws[r * 68 + c * 4] =
                *(const float4*)(wwu + (size_t)r * KINd + i0 + c * 4);
        }
        for (int q = t; q < 2048; q += 256) {
            int r = q >> 4, c = q & 15;
            *(float4*)&xsh[r * 68 + c * 4] =
                *(const float4*)(x + (size_t)(b0 + r) * KINd + i0 + c * 4);
        }
        if (t < 16) *(float4*)&bws[t * 4] = *(const float4*)(bwu + i0 + t * 4);
        __syncthreads();

#pragma unroll
        for (int rp = 0; rp < 4; ++rp)
#pragma unroll
            for (int j = 0; j < 4; ++j) acc2[rp][j] = 0ULL;

#pragma unroll 4
        for (int g = 0; g < 64; ++g) {
            ulonglong2 ha = *(const ulonglong2*)(h2tf + g * 132 + ty * 8);
            ulonglong2 hb = *(const ulonglong2*)(h2tf + g * 132 + ty * 8 + 4);
            float4 wv = *(const float4*)&wws[g * 68 + tx * 4];
            ull w0 = pack2(wv.x, wv.x), w1p = pack2(wv.y, wv.y);
            ull w2p = pack2(wv.z, wv.z), w3p = pack2(wv.w, wv.w);
            ffma2(acc2[0][0], ha.x, w0); ffma2(acc2[0][1], ha.x, w1p);
            ffma2(acc2[0][2], ha.x, w2p); ffma2(acc2[0][3], ha.x, w3p);
            ffma2(acc2[1][0], ha.y, w0); ffma2(acc2[1][1], ha.y, w1p);
            ffma2(acc2[1][2], ha.y, w2p); ffma2(acc2[1][3], ha.y, w3p);
            ffma2(acc2[2][0], hb.x, w0); ffma2(acc2[2][1], hb.x, w1p);
            ffma2(acc2[2][2], hb.x, w2p); ffma2(acc2[2][3], hb.x, w3p);
            ffma2(acc2[3][0], hb.y, w0); ffma2(acc2[3][1], hb.y, w1p);
            ffma2(acc2[3][2], hb.y, w2p); ffma2(acc2[3][3], hb.y, w3p);
        }

#pragma unroll
        for (int j = 0; j < 4; ++j) {
            float bwv = bws[tx * 4 + j];
#pragma unroll
            for (int rp = 0; rp < 4; ++rp) {
                float s0, s1;
                unpack2(acc2[rp][j], s0, s1);
                float p0 = sp_poly(s0 + bwv);
                float p1 = sp_poly(s1 + bwv);
                part[2 * rp]     += p0 * xsh[(ty * 8 + 2 * rp) * 68 + tx * 4 + j];
                part[2 * rp + 1] += p1 * xsh[(ty * 8 + 2 * rp + 1) * 68 + tx * 4 + j];
            }
        }
    }

#pragma unroll
    for (int gg = 0; gg < 4; ++gg) {
        int g = tx * 4 + gg;
        float swv = sWbs[g];
#pragma unroll
        for (int r = 0; r < 8; ++r)
            part[r] += h2tf[g * 132 + ty * 8 + r] * swv;
    }
#pragma unroll
    for (int r = 0; r < 8; ++r)
#pragma unroll
        for (int o = 8; o > 0; o >>= 1)
            part[r] += __shfl_down_sync(0xffffffffu, part[r], o, 16);
    if (tx == 0) {
        float sbbv = g_sbb[u];
#pragma unroll
        for (int r = 0; r < 8; ++r)
            g_inner[(size_t)(b0 + ty * 8 + r) * 2 + u] = part[r] + sbbv;
    }
}

// outer MLP: out[b] += wk * kan_out[b]; thread = (b, v, f-half)
__global__ void __launch_bounds__(512) outer_kernel(const float* __restrict__ ow1,
                                                    const float* __restrict__ ob1,
                                                    const float* __restrict__ ow2,
                                                    const float* __restrict__ ob2,
                                                    const float* __restrict__ oww,
                                                    const float* __restrict__ obw,
                                                    const float* __restrict__ owb,
                                                    const float* __restrict__ obb,
                                                    const float* __restrict__ wk,
                                                    float* __restrict__ out) {
    extern __shared__ char dynsm[];
    float* OW2f = (float*)dynsm;   // [2][128][68]
    __shared__ float w1as[2][128], w1bs[2][128], b1s[2][128];
    __shared__ float ob2s[2][64], owws[2][64], owbs[2][64];
    const int t = threadIdx.x;
    const int bl = t >> 2;
    const int v = (t >> 1) & 1;
    const int hf = t & 1;
    const int b = blockIdx.x * 128 + bl;

    for (int q = t; q < 4096; q += 512) {
        int vv = q >> 11, f = (q >> 4) & 127, c = q & 15;
        *(float4*)&OW2f[(vv * 128 + f) * 68 + c * 4] =
            *(const float4*)(ow2 + ((size_t)vv * 128 + f) * 64 + c * 4);
    }
    if (t < 256) {
        int vv = t >> 7, f = t & 127;
        w1as[vv][f] = ow1[(vv * 2 + 0) * 128 + f];
        w1bs[vv][f] = ow1[(vv * 2 + 1) * 128 + f];
        b1s[vv][f]  = ob1[vv * 128 + f];
    }
    if (t < 128) {
        int vv = t >> 6, j = t & 63;
        ob2s[vv][j] = ob2[vv * 64 + j];
        owws[vv][j] = oww[vv * 64 + j];
        owbs[vv][j] = owb[vv * 64 + j];
    }
    __syncthreads();

    const float i0 = g_inner[(size_t)b * 2 + 0];
    const float i1 = g_inner[(size_t)b * 2 + 1];

    ull g2a[32];
#pragma unroll
    for (int j = 0; j < 32; ++j)
        g2a[j] = (hf == 0) ? pack2(ob2s[v][2 * j], ob2s[v][2 * j + 1]) : 0ULL;

    const float* OW2v = OW2f + v * 128 * 68;
#pragma unroll 2
    for (int ff = 0; ff < 64; ++ff) {
        int f = hf * 64 + ff;
        float g1f = fmaxf(fmaf(i0, w1as[v][f], fmaf(i1, w1bs[v][f], b1s[v][f])), 0.f);
        ull g1p = pack2(g1f, g1f);
        const ull* row = (const ull*)(OW2v + f * 68);
#pragma unroll
        for (int j = 0; j < 32; ++j) ffma2(g2a[j], g1p, row[j]);
    }
#pragma unroll
    for (int j = 0; j < 32; ++j) {
        ull o = __shfl_xor_sync(0xffffffffu, g2a[j], 1);
        add2(g2a[j], o);
    }
    float sw = 0.f, sb = 0.f;
#pragma unroll
    for (int j = 0; j < 32; ++j) {
        float a, c2;
        unpack2(g2a[j], a, c2);
        a = fmaxf(a, 0.f); c2 = fmaxf(c2, 0.f);
        sw += a * owws[v][2 * j] + c2 * owws[v][2 * j + 1];
        sb += a * owbs[v][2 * j] + c2 * owbs[v][2 * j + 1];
    }
    float wout = sp_poly(sw + obw[v]);
    float bout = sb + obb[v];
    float term = wout * (i0 + i1) + 2.f * bout;
    term += __shfl_xor_sync(0xffffffffu, term, 2);
    if ((t & 3) == 0) out[b] += wk[0] * term;
}

extern "C" void kernel_launch(void* const* d_in, const int* in_sizes, int n_in,
                              void* d_out, int out_size) {
    const float* x_kan   = (const float*)d_in[0];
    const float* x_mamba = (const float*)d_in[1];
    const float* in_w1 = (const float*)d_in[2];
    const float* in_b1 = (const float*)d_in[3];
    const float* in_w2 = (const float*)d_in[4];
    const float* in_b2 = (const float*)d_in[5];
    const float* in_ww = (const float*)d_in[6];
    const float* in_bw = (const float*)d_in[7];
    const float* in_wb = (const float*)d_in[8];
    const float* in_bb = (const float*)d_in[9];
    const float* out_w1 = (const float*)d_in[10];
    const float* out_b1 = (const float*)d_in[11];
    const float* out_w2 = (const float*)d_in[12];
    const float* out_b2 = (const float*)d_in[13];
    const float* out_ww = (const float*)d_in[14];
    const float* out_bw = (const float*)d_in[15];
    const float* out_wb = (const float*)d_in[16];
    const float* out_bb = (const float*)d_in[17];
    const float* A      = (const float*)d_in[18];
    const float* B_ssm  = (const float*)d_in[19];
    const float* C_ssm  = (const float*)d_in[20];
    const float* wk     = (const float*)d_in[21];
    const float* wm     = (const float*)d_in[22];
    float* out = (float*)d_out;

    const int APSMEM = (256 * 34 + 256 * 36) * 4;                        // 71680
    const int G1SMEM = (128 * 36 + 32 * 128) * 4;                        // 34816
    const int S2SMEM = (64 * 132 + 64 * 68 + 128 * 68 + 64 + 64) * 4;    // 86528
    const int OSMEM  = 2 * 128 * 68 * 4;                                  // 69632
    cudaFuncSetAttribute(apow_kernel, cudaFuncAttributeMaxDynamicSharedMemorySize, APSMEM);
    cudaFuncSetAttribute(stage2_kernel, cudaFuncAttributeMaxDynamicSharedMemorySize, S2SMEM);
    cudaFuncSetAttribute(outer_kernel, cudaFuncAttributeMaxDynamicSharedMemorySize, OSMEM);

    // virtual grid for g1mamba: 256 gemm1 + 2048 mamba = 2304 blocks, 3 splits
    ksums_kernel<<<130, 32>>>(in_wb, in_bb);                          // 1 (+ctr reset)
    apow_kernel<<<64, 256, APSMEM>>>(A);                              // 2 (A^2..A^64)
    vand_kernel<<<8, 256>>>(A, B_ssm, C_ssm);                         // 3 (g_M)
    g1mamba_kernel<<<768, 256, G1SMEM>>>(x_kan, in_w1, in_b1,
                                         x_mamba, wm, out, 0);        // 4
    g1mamba_kernel<<<768, 256, G1SMEM>>>(x_kan, in_w1, in_b1,
                                         x_mamba, wm, out, 768);      // 5
    g1mamba_kernel<<<768, 256, G1SMEM>>>(x_kan, in_w1, in_b1,
                                         x_mamba, wm, out, 1536);     // 6
    gemm2_kernel<<<dim3(2, Bn / 64), 256>>>(in_w2, in_b2);            // 7
    stage2_kernel<<<dim3(2, Bn / 128), 256, S2SMEM>>>(x_kan, in_ww, in_bw); // 8
    outer_kernel<<<Bn / 128, 512, OSMEM>>>(out_w1, out_b1, out_w2, out_b2,
                                           out_ww, out_bw, out_wb, out_bb, wk, out); // 9
}

// round 9
// speedup vs baseline: 1.1448x; 1.1448x over previous
#include <cuda_runtime.h>
#include <math.h>
#include <cstdint>

#define Bn    16384
#define KINd  1024
#define MINd  64
#define Sd    256
#define Td    128
#define H1d   128
#define H2d   64

typedef unsigned long long ull;

// ------------------------- scratch (device globals; no allocs) --------------
static __device__ __align__(16) float g_Pw[6 * Sd * Sd];   // A^2,4,8,16,32,64
static __device__ __align__(16) float g_S[Sd * 128];       // Krylov cols A^n c
static __device__ __align__(16) float g_BT[Sd * MINd];     // B^T
static __device__ __align__(16) float g_M[Td * MINd];
static __device__ __align__(16) float g_h1[(size_t)Bn * 2 * H1d];   // 16 MB
static __device__ __align__(16) float g_h2[(size_t)Bn * 2 * H2d];   // 8 MB
static __device__ __align__(16) float g_inner[(size_t)Bn * 2];
static __device__ __align__(16) unsigned short g_w1h[2 * H1d * KINd]; // W1^T hi bf16
static __device__ __align__(16) unsigned short g_w1l[2 * H1d * KINd]; // W1^T lo bf16
static __device__ float g_sWb[2 * H2d];
static __device__ float g_sbb[2];
static __device__ volatile int g_sync[16];

// ---- FMA-only softplus (no MUFU) -------------------------------------------
__device__ __forceinline__ float sp_poly(float s) {
    float t = fmaxf(-fabsf(s), -17.f);
    float z = t * 1.44269504f;
    int   ni = __float2int_rn(z);
    float f = z - (float)ni;
    float p = 1.33335581e-3f;
    p = fmaf(p, f, 9.61812911e-3f);
    p = fmaf(p, f, 5.55041087e-2f);
    p = fmaf(p, f, 2.40226507e-1f);
    p = fmaf(p, f, 6.93147181e-1f);
    p = fmaf(p, f, 1.f);
    float y = __int_as_float((ni + 127) << 23) * p;
    float v = 2.f + y;
    float r0 = fmaf(-0.1716f, v, 0.8249f);
    r0 = r0 * fmaf(-v, r0, 2.f);
    r0 = r0 * fmaf(-v, r0, 2.f);
    float r  = y * r0;
    float r2 = r * r;
    float q = fmaf(r2, 0.28571429f, 0.4f);
    q = fmaf(r2, q, 0.66666667f);
    q = fmaf(r2, q, 2.f);
    return fmaxf(s, 0.f) + r * q;
}

// ---- packed f32x2 helpers ---------------------------------------------------
__device__ __forceinline__ void ffma2(ull& d, ull a, ull b) {
    asm("fma.rn.f32x2 %0, %1, %2, %0;" : "+l"(d) : "l"(a), "l"(b));
}
__device__ __forceinline__ void add2(ull& d, ull o) {
    asm("add.rn.f32x2 %0, %0, %1;" : "+l"(d) : "l"(o));
}
__device__ __forceinline__ ull pack2(float lo, float hi) {
    ull r; asm("mov.b64 %0, {%1, %2};" : "=l"(r) : "f"(lo), "f"(hi)); return r;
}
__device__ __forceinline__ void unpack2(ull v, float& lo, float& hi) {
    asm("mov.b64 {%0, %1}, %2;" : "=f"(lo), "=f"(hi) : "l"(v));
}

// ---- bf16 helpers ------------------------------------------------------------
__device__ __forceinline__ uint32_t packbf2(float x_lo16, float x_hi16) {
    // result: lower 16 bits = bf16(x_lo16), upper = bf16(x_hi16)
    uint32_t r;
    asm("cvt.rn.bf16x2.f32 %0, %1, %2;" : "=r"(r) : "f"(x_hi16), "f"(x_lo16));
    return r;
}
__device__ __forceinline__ unsigned short f2bf(float v) {
    unsigned short r; asm("cvt.rn.bf16.f32 %0, %1;" : "=h"(r) : "f"(v)); return r;
}

// ---- warp mma m16n8k16 bf16 --------------------------------------------------
__device__ __forceinline__ void mma_bf16(float* d, const uint32_t* a,
                                         uint32_t b0, uint32_t b1) {
    asm volatile(
        "mma.sync.aligned.m16n8k16.row.col.f32.bf16.bf16.f32 "
        "{%0,%1,%2,%3}, {%4,%5,%6,%7}, {%8,%9}, {%0,%1,%2,%3};"
        : "+f"(d[0]), "+f"(d[1]), "+f"(d[2]), "+f"(d[3])
        : "r"(a[0]), "r"(a[1]), "r"(a[2]), "r"(a[3]), "r"(b0), "r"(b1));
}

// ---- resident-grid sync (counters reset by ksums each replay) ---------------
__device__ __forceinline__ void grid_sync(int s, int n) {
    __threadfence();
    __syncthreads();
    if (threadIdx.x == 0) {
        atomicAdd((int*)&g_sync[s], 1);
        while (*(volatile int*)&g_sync[s] < n) { }
        __threadfence();
    }
    __syncthreads();
}

// ------------------------- A^(2^s), s=1..6, one kernel -----------------------
__global__ void __launch_bounds__(256) apow_kernel(const float* __restrict__ A) {
    extern __shared__ char dynsm[];
    float* As = (float*)dynsm;
    float* Bs = (float*)dynsm + 256 * 34;
    const int t = threadIdx.x, tx = t & 15, ty = t >> 4;
    const int rb = (blockIdx.x >> 3) * 32, cb = (blockIdx.x & 7) * 32;

#pragma unroll
    for (int s = 0; s < 6; ++s) {
        const float* L = (s == 0) ? A : g_Pw + (size_t)(s - 1) * Sd * Sd;
        float* C = g_Pw + (size_t)s * Sd * Sd;
        for (int q = t; q < 2048; q += 256) {
            int i = q >> 6, k4 = (q & 63) * 4;
            float4 v = *(const float4*)(L + (size_t)(rb + i) * Sd + k4);
            As[(k4 + 0) * 34 + i] = v.x;
            As[(k4 + 1) * 34 + i] = v.y;
            As[(k4 + 2) * 34 + i] = v.z;
            As[(k4 + 3) * 34 + i] = v.w;
        }
        for (int q = t; q < 2048; q += 256) {
            int k = q >> 3, j4 = (q & 7) * 4;
            *(float4*)&Bs[k * 36 + j4] = *(const float4*)(L + (size_t)k * Sd + cb + j4);
        }
        __syncthreads();
        float c00 = 0.f, c01 = 0.f, c10 = 0.f, c11 = 0.f;
#pragma unroll 8
        for (int k = 0; k < 256; ++k) {
            float2 av = *(float2*)&As[k * 34 + ty * 2];
            float2 bv = *(float2*)&Bs[k * 36 + tx * 2];
            c00 += av.x * bv.x; c01 += av.x * bv.y;
            c10 += av.y * bv.x; c11 += av.y * bv.y;
        }
        C[(size_t)(rb + ty * 2) * Sd + cb + tx * 2]         = c00;
        C[(size_t)(rb + ty * 2) * Sd + cb + tx * 2 + 1]     = c01;
        C[(size_t)(rb + ty * 2 + 1) * Sd + cb + tx * 2]     = c10;
        C[(size_t)(rb + ty * 2 + 1) * Sd + cb + tx * 2 + 1] = c11;
        if (s < 5) {
            grid_sync(s, 64);
            __syncthreads();
        }
    }
}

// ---- Vandermonde doubling: S=[c, Ac, ..., A^127 c], then M = B@S(reversed) --
__global__ void __launch_bounds__(256) vand_kernel(const float* __restrict__ A,
                                                   const float* __restrict__ Bssm,
                                                   const float* __restrict__ Cssm) {
    const int t = threadIdx.x;
    const int gtid = blockIdx.x * 256 + t;
    const int nth = 8 * 256;

    for (int idx = gtid; idx < MINd * Sd; idx += nth) {
        int m = idx >> 8, j = idx & 255;
        g_BT[j * MINd + m] = Bssm[idx];
    }
    for (int idx = gtid; idx < Sd; idx += nth) g_S[idx * 128] = Cssm[idx];
    grid_sync(5, 8);

    int width = 1;
#pragma unroll
    for (int k = 0; k < 7; ++k) {
        const float* Pk = (k == 0) ? A : g_Pw + (size_t)(k - 1) * Sd * Sd;
        const int nout = Sd * width;
        for (int idx = gtid; idx < nout; idx += nth) {
            const int i = idx >> k;
            const int cc = idx & (width - 1);
            const float* prow = Pk + (size_t)i * Sd;
            float a0 = 0.f, a1 = 0.f, a2 = 0.f, a3 = 0.f;
#pragma unroll 4
            for (int j = 0; j < 256; j += 4) {
                a0 += prow[j + 0] * __ldcg(g_S + (j + 0) * 128 + cc);
                a1 += prow[j + 1] * __ldcg(g_S + (j + 1) * 128 + cc);
                a2 += prow[j + 2] * __ldcg(g_S + (j + 2) * 128 + cc);
                a3 += prow[j + 3] * __ldcg(g_S + (j + 3) * 128 + cc);
            }
            g_S[(size_t)i * 128 + width + cc] = (a0 + a1) + (a2 + a3);
        }
        grid_sync(6 + k, 8);
        width <<= 1;
    }

    for (int idx = gtid; idx < Td * MINd; idx += nth) {
        const int tau = idx >> 6, m = idx & 63;
        const int col = 127 - tau;
        float a0 = 0.f, a1 = 0.f;
#pragma unroll 4
        for (int j = 0; j < 256; j += 2) {
            a0 += g_BT[(j + 0) * MINd + m] * __ldcg(g_S + (j + 0) * 128 + col);
            a1 += g_BT[(j + 1) * MINd + m] * __ldcg(g_S + (j + 1) * 128 + col);
        }
        g_M[idx] = a0 + a1;
    }
}

// ---- W1 bf16 hi/lo split + transpose to [u][n][k] ---------------------------
__global__ void __launch_bounds__(128) wsplit_kernel(const float* __restrict__ w1,
                                                     int u) {
    const int n = blockIdx.x;
    const int t = threadIdx.x;
    for (int k = t; k < KINd; k += 128) {
        float v = w1[((size_t)u * KINd + k) * H1d + n];
        unsigned short h = f2bf(v);
        float hf = __uint_as_float((uint32_t)h << 16);
        unsigned short l = f2bf(v - hf);
        size_t o = ((size_t)u * H1d + n) * KINd + k;
        g_w1h[o] = h;
        g_w1l[o] = l;
    }
}

// row-sums of in_wb / in_bb (bias-collapse) + sync-counter reset for replays
__global__ void ksums_kernel(const float* __restrict__ wb,
                             const float* __restrict__ bb) {
    int r = blockIdx.x, lane = threadIdx.x;
    if (r == 0 && lane == 0) {
#pragma unroll
        for (int s = 0; s < 16; ++s) g_sync[s] = 0;
    }
    float s = 0.f;
    if (r < 128) {
        const float* row = wb + (size_t)r * KINd;
        for (int i = lane; i < KINd; i += 32) s += row[i];
    } else if (r < 130) {
        const float* row = bb + (size_t)(r - 128) * KINd;
        for (int i = lane; i < KINd; i += 32) s += row[i];
    }
#pragma unroll
    for (int o = 16; o > 0; o >>= 1) s += __shfl_down_sync(0xffffffffu, s, o);
    if (lane == 0) {
        if (r < 128) g_sWb[r] = s;
        else if (r < 130) g_sbb[r - 128] = s;
    }
}

// ---------- combined kernel: gemm1-mma (blocks 0..255) + mamba (256..2303) ---
// gemm1: h1 = relu(x @ W1[u] + b1[u]) via bf16-split mma.sync (HMMA).
#define XSTR 70   // bf16 stride (140 B) -> conflict-free quad loads
__global__ void __launch_bounds__(256, 2) g1mamba_kernel(const float* __restrict__ x,
                                                         const float* __restrict__ b1,
                                                         const float* __restrict__ xm,
                                                         const float* __restrict__ wm,
                                                         float* __restrict__ out) {
    extern __shared__ char dynsm[];
    const int vb = blockIdx.x;
    const int t = threadIdx.x;

    if (vb < 256) {
        // ---- gemm1 mma path ----
        unsigned short* xh = (unsigned short*)dynsm;                  // [128][70]
        unsigned short* xl = xh + 128 * XSTR;
        unsigned short* wh = xl + 128 * XSTR;                         // [128n][70]
        unsigned short* wl = wh + 128 * XSTR;
        float* bias_sm = (float*)(wl + 128 * XSTR);                   // [128]
        const int u = vb & 1;
        const int b0 = (vb >> 1) * 128;
        const int warp = t >> 5, lane = t & 31;
        const int g = lane >> 2, tq = lane & 3;
        const int row_base = (warp >> 1) * 32;
        const int col_base = (warp & 1) * 64;
        const unsigned short* gwh = g_w1h + (size_t)u * H1d * KINd;
        const unsigned short* gwl = g_w1l + (size_t)u * H1d * KINd;

        if (t < 128) bias_sm[t] = b1[u * H1d + t];

        float acc[2][8][4];
#pragma unroll
        for (int s = 0; s < 2; ++s)
#pragma unroll
            for (int tl = 0; tl < 8; ++tl)
#pragma unroll
                for (int r = 0; r < 4; ++r) acc[s][tl][r] = 0.f;

        for (int ch = 0; ch < 16; ++ch) {
            const int k0 = ch * 64;
            if (ch) __syncthreads();   // protect smem reuse
            // x chunk: f32 -> bf16 hi/lo
            for (int q = t; q < 4096; q += 256) {
                int row = q >> 5, kp = (q & 31) * 2;
                float2 v = *(const float2*)(x + (size_t)(b0 + row) * KINd + k0 + kp);
                uint32_t hp = packbf2(v.x, v.y);
                float h0 = __uint_as_float(hp << 16);
                float h1 = __uint_as_float(hp & 0xFFFF0000u);
                uint32_t lp = packbf2(v.x - h0, v.y - h1);
                int idx = row * XSTR + kp;
                *(uint32_t*)(xh + idx) = hp;
                *(uint32_t*)(xl + idx) = lp;
            }
            // w chunk: precomputed bf16, copy
            for (int q = t; q < 4096; q += 256) {
                int n = q >> 5, kp = (q & 31) * 2;
                size_t src = (size_t)n * KINd + k0 + kp;
                int idx = n * XSTR + kp;
                *(uint32_t*)(wh + idx) = *(const uint32_t*)(gwh + src);
                *(uint32_t*)(wl + idx) = *(const uint32_t*)(gwl + src);
            }
            __syncthreads();

#pragma unroll
            for (int s16 = 0; s16 < 4; ++s16) {
                const int kb = s16 * 16;
                uint32_t ah[2][4], al[2][4];
#pragma unroll
                for (int st = 0; st < 2; ++st) {
                    int base = (row_base + st * 16 + g) * XSTR + kb + 2 * tq;
                    ah[st][0] = *(uint32_t*)(xh + base);
                    ah[st][1] = *(uint32_t*)(xh + base + 8 * XSTR);
                    ah[st][2] = *(uint32_t*)(xh + base + 8);
                    ah[st][3] = *(uint32_t*)(xh + base + 8 * XSTR + 8);
                    al[st][0] = *(uint32_t*)(xl + base);
                    al[st][1] = *(uint32_t*)(xl + base + 8 * XSTR);
                    al[st][2] = *(uint32_t*)(xl + base + 8);
                    al[st][3] = *(uint32_t*)(xl + base + 8 * XSTR + 8);
                }
#pragma unroll
                for (int tl = 0; tl < 8; ++tl) {
                    int bbase = (col_base + tl * 8 + g) * XSTR + kb + 2 * tq;
                    uint32_t bh0 = *(uint32_t*)(wh + bbase);
                    uint32_t bh1 = *(uint32_t*)(wh + bbase + 8);
                    uint32_t bl0 = *(uint32_t*)(wl + bbase);
                    uint32_t bl1 = *(uint32_t*)(wl + bbase + 8);
#pragma unroll
                    for (int st = 0; st < 2; ++st) {
                        mma_bf16(acc[st][tl], ah[st], bh0, bh1);
                        mma_bf16(acc[st][tl], ah[st], bl0, bl1);
                        mma_bf16(acc[st][tl], al[st], bh0, bh1);
                    }
                }
            }
        }

        // epilogue: bias + relu, store
#pragma unroll
        for (int st = 0; st < 2; ++st) {
            int r0 = row_base + st * 16 + g;
#pragma unroll
            for (int tl = 0; tl < 8; ++tl) {
                int c = col_base + tl * 8 + 2 * tq;
                float bz0 = bias_sm[c], bz1 = bias_sm[c + 1];
                float2 o;
                o.x = fmaxf(acc[st][tl][0] + bz0, 0.f);
                o.y = fmaxf(acc[st][tl][1] + bz1, 0.f);
                *(float2*)(g_h1 + ((size_t)(b0 + r0) * 2 + u) * H1d + c) = o;
                o.x = fmaxf(acc[st][tl][2] + bz0, 0.f);
                o.y = fmaxf(acc[st][tl][3] + bz1, 0.f);
                *(float2*)(g_h1 + ((size_t)(b0 + r0 + 8) * 2 + u) * H1d + c) = o;
            }
        }
    } else {
        // ---- mamba path: 8 warps, one row each ----
        float4* Ms = (float4*)dynsm;     // 2048 float4 = 32 KB
        const float4* Mg = (const float4*)g_M;
        for (int q = t; q < 2048; q += 256) Ms[q] = Mg[q];
        __syncthreads();
        const int warp = t >> 5, lane = t & 31;
        const int b = (vb - 256) * 8 + warp;
        const float4* xr = (const float4*)(xm + (size_t)b * (Td * MINd));
        float acc = 0.f;
#pragma unroll 8
        for (int j = lane; j < 2048; j += 32) {
            float4 xv = xr[j];
            float4 mv = Ms[j];
            acc += xv.x * mv.x + xv.y * mv.y + xv.z * mv.z + xv.w * mv.w;
        }
#pragma unroll
        for (int o = 16; o > 0; o >>= 1) acc += __shfl_down_sync(0xffffffffu, acc, o);
        if (lane == 0) out[b] = wm[0] * acc;
    }
}

// h2 = relu(h1 @ W2[u] + b2[u])
__global__ void __launch_bounds__(256) gemm2_kernel(const float* __restrict__ w2,
                                                    const float* __restrict__ b2) {
    __shared__ float hs[64][65];
    __shared__ float w2s[64][64];
    const int u = blockIdx.x;
    const int b0 = blockIdx.y * 64;
    const int t = threadIdx.x;
    const int tx = t & 15;
    const int ty = t >> 4;
    const float* w2u = w2 + (size_t)u * H1d * H2d;

    float acc[4][4];
#pragma unroll
    for (int i = 0; i < 4; ++i)
#pragma unroll
        for (int j = 0; j < 4; ++j) acc[i][j] = 0.f;

    for (int k0 = 0; k0 < H1d; k0 += 64) {
        for (int q = t; q < 1024; q += 256) {
            int r = q >> 4, c = q & 15;
            float4 v = *(const float4*)(g_h1 + ((size_t)(b0 + r) * 2 + u) * H1d + k0 + c * 4);
            hs[r][c * 4 + 0] = v.x; hs[r][c * 4 + 1] = v.y;
            hs[r][c * 4 + 2] = v.z; hs[r][c * 4 + 3] = v.w;
        }
        for (int q = t; q < 1024; q += 256) {
            int r = q >> 4, c = q & 15;
            *(float4*)&w2s[r][c * 4] = *(const float4*)(w2u + (size_t)(k0 + r) * H2d + c * 4);
        }
        __syncthreads();
#pragma unroll 8
        for (int f = 0; f < 64; ++f) {
            float4 w = *(float4*)&w2s[f][tx * 4];
            float a0 = hs[ty * 4 + 0][f];
            float a1 = hs[ty * 4 + 1][f];
            float a2 = hs[ty * 4 + 2][f];
            float a3 = hs[ty * 4 + 3][f];
            acc[0][0] += a0 * w.x; acc[0][1] += a0 * w.y; acc[0][2] += a0 * w.z; acc[0][3] += a0 * w.w;
            acc[1][0] += a1 * w.x; acc[1][1] += a1 * w.y; acc[1][2] += a1 * w.z; acc[1][3] += a1 * w.w;
            acc[2][0] += a2 * w.x; acc[2][1] += a2 * w.y; acc[2][2] += a2 * w.z; acc[2][3] += a2 * w.w;
            acc[3][0] += a3 * w.x; acc[3][1] += a3 * w.y; acc[3][2] += a3 * w.z; acc[3][3] += a3 * w.w;
        }
        __syncthreads();
    }
#pragma unroll
    for (int i = 0; i < 4; ++i) {
        int b = b0 + ty * 4 + i;
#pragma unroll
        for (int j = 0; j < 4; ++j) {
            int g = tx * 4 + j;
            float v = acc[i][j] + b2[u * H2d + g];
            g_h2[((size_t)b * 2 + u) * H2d + g] = fmaxf(v, 0.f);
        }
    }
}

// inner[b,u] = sum_i softplus(h2.Ww[:,i]+bw[i])*x[b,i] + h2.sWb + sbb
__global__ void __launch_bounds__(256) stage2_kernel(const float* __restrict__ x,
                                                     const float* __restrict__ ww,
                                                     const float* __restrict__ bw) {
    extern __shared__ char dynsm[];
    float* h2tf = (float*)dynsm;           // [64][132]
    float* wws  = h2tf + 64 * 132;         // [64][68]
    float* xsh  = wws + 64 * 68;           // [128][68]
    float* bws  = xsh + 128 * 68;          // [64]
    float* sWbs = bws + 64;                // [64]
    const int u = blockIdx.x;
    const int b0 = blockIdx.y * 128;
    const int t = threadIdx.x;
    const int tx = t & 15;
    const int ty = t >> 4;
    const float* wwu = ww + (size_t)u * H2d * KINd;
    const float* bwu = bw + (size_t)u * KINd;

    if (t < 64) sWbs[t] = g_sWb[u * H2d + t];
    for (int q = t; q < 2048; q += 256) {
        int r = q & 127, gq = (q >> 7) * 4;
        float4 v = *(const float4*)(g_h2 + ((size_t)(b0 + r) * 2 + u) * H2d + gq);
        h2tf[(gq + 0) * 132 + r] = v.x;
        h2tf[(gq + 1) * 132 + r] = v.y;
        h2tf[(gq + 2) * 132 + r] = v.z;
        h2tf[(gq + 3) * 132 + r] = v.w;
    }
    __syncthreads();

    ull acc2[4][4];
    float part[8];
#pragma unroll
    for (int r = 0; r < 8; ++r) part[r] = 0.f;

    for (int it = 0; it < 16; ++it) {
        int i0 = it * 64;
        __syncthreads();
        for (int q = t; q < 1024; q += 256) {
            int r = q >> 4, c = q & 15;
            *(float4*)&wws[r * 68 + c * 4] =
                *(const float4*)(wwu + (size_t)r * KINd + i0 + c * 4);
        }
        for (int q = t; q < 2048; q += 256) {
            int r = q >> 4, c = q & 15;
            *(float4*)&xsh[r * 68 + c * 4] =
                *(const float4*)(x + (size_t)(b0 + r) * KINd + i0 + c * 4);
        }
        if (t < 16) *(float4*)&bws[t * 4] = *(const float4*)(bwu + i0 + t * 4);
        __syncthreads();

#pragma unroll
        for (int rp = 0; rp < 4; ++rp)
#pragma unroll
            for (int j = 0; j < 4; ++j) acc2[rp][j] = 0ULL;

#pragma unroll 4
        for (int g = 0; g < 64; ++g) {
            ulonglong2 ha = *(const ulonglong2*)(h2tf + g * 132 + ty * 8);
            ulonglong2 hb = *(const ulonglong2*)(h2tf + g * 132 + ty * 8 + 4);
            float4 wv = *(const float4*)&wws[g * 68 + tx * 4];
            ull w0 = pack2(wv.x, wv.x), w1p = pack2(wv.y, wv.y);
            ull w2p = pack2(wv.z, wv.z), w3p = pack2(wv.w, wv.w);
            ffma2(acc2[0][0], ha.x, w0); ffma2(acc2[0][1], ha.x, w1p);
            ffma2(acc2[0][2], ha.x, w2p); ffma2(acc2[0][3], ha.x, w3p);
            ffma2(acc2[1][0], ha.y, w0); ffma2(acc2[1][1], ha.y, w1p);
            ffma2(acc2[1][2], ha.y, w2p); ffma2(acc2[1][3], ha.y, w3p);
            ffma2(acc2[2][0], hb.x, w0); ffma2(acc2[2][1], hb.x, w1p);
            ffma2(acc2[2][2], hb.x, w2p); ffma2(acc2[2][3], hb.x, w3p);
            ffma2(acc2[3][0], hb.y, w0); ffma2(acc2[3][1], hb.y, w1p);
            ffma2(acc2[3][2], hb.y, w2p); ffma2(acc2[3][3], hb.y, w3p);
        }

#pragma unroll
        for (int j = 0; j < 4; ++j) {
            float bwv = bws[tx * 4 + j];
#pragma unroll
            for (int rp = 0; rp < 4; ++rp) {
                float s0, s1;
                unpack2(acc2[rp][j], s0, s1);
                float p0 = sp_poly(s0 + bwv);
                float p1 = sp_poly(s1 + bwv);
                part[2 * rp]     += p0 * xsh[(ty * 8 + 2 * rp) * 68 + tx * 4 + j];
                part[2 * rp + 1] += p1 * xsh[(ty * 8 + 2 * rp + 1) * 68 + tx * 4 + j];
            }
        }
    }

#pragma unroll
    for (int gg = 0; gg < 4; ++gg) {
        int g = tx * 4 + gg;
        float swv = sWbs[g];
#pragma unroll
        for (int r = 0; r < 8; ++r)
            part[r] += h2tf[g * 132 + ty * 8 + r] * swv;
    }
#pragma unroll
    for (int r = 0; r < 8; ++r)
#pragma unroll
        for (int o = 8; o > 0; o >>= 1)
            part[r] += __shfl_down_sync(0xffffffffu, part[r], o, 16);
    if (tx == 0) {
        float sbbv = g_sbb[u];
#pragma unroll
        for (int r = 0; r < 8; ++r)
            g_inner[(size_t)(b0 + ty * 8 + r) * 2 + u] = part[r] + sbbv;
    }
}

// outer MLP: out[b] += wk * kan_out[b]; thread = (b, v, f-half)
__global__ void __launch_bounds__(512) outer_kernel(const float* __restrict__ ow1,
                                                    const float* __restrict__ ob1,
                                                    const float* __restrict__ ow2,
                                                    const float* __restrict__ ob2,
                                                    const float* __restrict__ oww,
                                                    const float* __restrict__ obw,
                                                    const float* __restrict__ owb,
                                                    const float* __restrict__ obb,
                                                    const float* __restrict__ wk,
                                                    float* __restrict__ out) {
    extern __shared__ char dynsm[];
    float* OW2f = (float*)dynsm;   // [2][128][68]
    __shared__ float w1as[2][128], w1bs[2][128], b1s[2][128];
    __shared__ float ob2s[2][64], owws[2][64], owbs[2][64];
    const int t = threadIdx.x;
    const int bl = t >> 2;
    const int v = (t >> 1) & 1;
    const int hf = t & 1;
    const int b = blockIdx.x * 128 + bl;

    for (int q = t; q < 4096; q += 512) {
        int vv = q >> 11, f = (q >> 4) & 127, c = q & 15;
        *(float4*)&OW2f[(vv * 128 + f) * 68 + c * 4] =
            *(const float4*)(ow2 + ((size_t)vv * 128 + f) * 64 + c * 4);
    }
    if (t < 256) {
        int vv = t >> 7, f = t & 127;
        w1as[vv][f] = ow1[(vv * 2 + 0) * 128 + f];
        w1bs[vv][f] = ow1[(vv * 2 + 1) * 128 + f];
        b1s[vv][f]  = ob1[vv * 128 + f];
    }
    if (t < 128) {
        int vv = t >> 6, j = t & 63;
        ob2s[vv][j] = ob2[vv * 64 + j];
        owws[vv][j] = oww[vv * 64 + j];
        owbs[vv][j] = owb[vv * 64 + j];
    }
    __syncthreads();

    const float i0 = g_inner[(size_t)b * 2 + 0];
    const float i1 = g_inner[(size_t)b * 2 + 1];

    ull g2a[32];
#pragma unroll
    for (int j = 0; j < 32; ++j)
        g2a[j] = (hf == 0) ? pack2(ob2s[v][2 * j], ob2s[v][2 * j + 1]) : 0ULL;

    const float* OW2v = OW2f + v * 128 * 68;
#pragma unroll 2
    for (int ff = 0; ff < 64; ++ff) {
        int f = hf * 64 + ff;
        float g1f = fmaxf(fmaf(i0, w1as[v][f], fmaf(i1, w1bs[v][f], b1s[v][f])), 0.f);
        ull g1p = pack2(g1f, g1f);
        const ull* row = (const ull*)(OW2v + f * 68);
#pragma unroll
        for (int j = 0; j < 32; ++j) ffma2(g2a[j], g1p, row[j]);
    }
#pragma unroll
    for (int j = 0; j < 32; ++j) {
        ull o = __shfl_xor_sync(0xffffffffu, g2a[j], 1);
        add2(g2a[j], o);
    }
    float sw = 0.f, sb = 0.f;
#pragma unroll
    for (int j = 0; j < 32; ++j) {
        float a, c2;
        unpack2(g2a[j], a, c2);
        a = fmaxf(a, 0.f); c2 = fmaxf(c2, 0.f);
        sw += a * owws[v][2 * j] + c2 * owws[v][2 * j + 1];
        sb += a * owbs[v][2 * j] + c2 * owbs[v][2 * j + 1];
    }
    float wout = sp_poly(sw + obw[v]);
    float bout = sb + obb[v];
    float term = wout * (i0 + i1) + 2.f * bout;
    term += __shfl_xor_sync(0xffffffffu, term, 2);
    if ((t & 3) == 0) out[b] += wk[0] * term;
}

extern "C" void kernel_launch(void* const* d_in, const int* in_sizes, int n_in,
                              void* d_out, int out_size) {
    const float* x_kan   = (const float*)d_in[0];
    const float* x_mamba = (const float*)d_in[1];
    const float* in_w1 = (const float*)d_in[2];
    const float* in_b1 = (const float*)d_in[3];
    const float* in_w2 = (const float*)d_in[4];
    const float* in_b2 = (const float*)d_in[5];
    const float* in_ww = (const float*)d_in[6];
    const float* in_bw = (const float*)d_in[7];
    const float* in_wb = (const float*)d_in[8];
    const float* in_bb = (const float*)d_in[9];
    const float* out_w1 = (const float*)d_in[10];
    const float* out_b1 = (const float*)d_in[11];
    const float* out_w2 = (const float*)d_in[12];
    const float* out_b2 = (const float*)d_in[13];
    const float* out_ww = (const float*)d_in[14];
    const float* out_bw = (const float*)d_in[15];
    const float* out_wb = (const float*)d_in[16];
    const float* out_bb = (const float*)d_in[17];
    const float* A      = (const float*)d_in[18];
    const float* B_ssm  = (const float*)d_in[19];
    const float* C_ssm  = (const float*)d_in[20];
    const float* wk     = (const float*)d_in[21];
    const float* wm     = (const float*)d_in[22];
    float* out = (float*)d_out;

    const int APSMEM = (256 * 34 + 256 * 36) * 4;                        // 71680
    const int G1SMEM = 4 * 128 * XSTR * 2 + 128 * 4;                     // 72192
    const int S2SMEM = (64 * 132 + 64 * 68 + 128 * 68 + 64 + 64) * 4;    // 86528
    const int OSMEM  = 2 * 128 * 68 * 4;                                  // 69632
    cudaFuncSetAttribute(apow_kernel, cudaFuncAttributeMaxDynamicSharedMemorySize, APSMEM);
    cudaFuncSetAttribute(g1mamba_kernel, cudaFuncAttributeMaxDynamicSharedMemorySize, G1SMEM);
    cudaFuncSetAttribute(stage2_kernel, cudaFuncAttributeMaxDynamicSharedMemorySize, S2SMEM);
    cudaFuncSetAttribute(outer_kernel, cudaFuncAttributeMaxDynamicSharedMemorySize, OSMEM);

    ksums_kernel<<<130, 32>>>(in_wb, in_bb);                          // 1 (+ctr reset)
    wsplit_kernel<<<128, 128>>>(in_w1, 0);                            // 2
    wsplit_kernel<<<128, 128>>>(in_w1, 1);                            // 3
    apow_kernel<<<64, 256, APSMEM>>>(A);                              // 4 (A^2..A^64)
    vand_kernel<<<8, 256>>>(A, B_ssm, C_ssm);                         // 5 (g_M)
    g1mamba_kernel<<<2304, 256, G1SMEM>>>(x_kan, in_b1,
                                          x_mamba, wm, out);          // 6 (profile target)
    gemm2_kernel<<<dim3(2, Bn / 64), 256>>>(in_w2, in_b2);            // 7
    stage2_kernel<<<dim3(2, Bn / 128), 256, S2SMEM>>>(x_kan, in_ww, in_bw); // 8
    outer_kernel<<<Bn / 128, 512, OSMEM>>>(out_w1, out_b1, out_w2, out_b2,
                                           out_ww, out_bw, out_wb, out_bb, wk, out); // 9
}